// round 13
// baseline (speedup 1.0000x reference)
#include <cuda_runtime.h>
#include <cstdint>

#define BB   4
#define CC   32
#define HH   256
#define WW   256
#define SSZ  16
#define NHH  16
#define NWW  16
#define SP   256
#define NPIX 65536

__device__ float g_cent[BB][SP][CC];
__device__ float g_pnum[BB][SP][9][CC];
__device__ float g_pden[BB][SP][9];

#define BARRIER_COMPUTE() asm volatile("bar.sync 1, 288;" ::: "memory")

__device__ __forceinline__ uint32_t smem_u32(const void* p) {
    uint32_t a;
    asm("{ .reg .u64 t; cvta.to.shared.u64 t, %1; cvt.u32.u64 %0, t; }"
        : "=r"(a) : "l"(p));
    return a;
}

// ---------------------------------------------------------------------------
// TMA band zero: one warp. Zero an 8KB smem buffer, then bulk-copy it over
// this (b,s) row's top/bottom zero bands slice [fracA, fracB) (per-mille,
// rounded to 1KB). Engine-drained: no LSU pressure, overlaps compute.
// ---------------------------------------------------------------------------
__device__ __forceinline__ void tma_zero_bands(float* __restrict__ out, int bs,
                                               int mA, int mB,  // per-mille
                                               float4* zb, int lane) {
    // zero the 8KB buffer (512 float4)
    const float4 z = make_float4(0.f, 0.f, 0.f, 0.f);
#pragma unroll
    for (int i = lane; i < 512; i += 32) zb[i] = z;
    __syncwarp();
    asm volatile("fence.proxy.async.shared::cta;" ::: "memory");
    if (lane == 0) {
        int s = bs & 255;
        int sy = s >> 4, sx = s & 15;
        int ny0 = max(sy - 1, 0), ny1 = min(sy + 1, NHH - 1);
        int y0 = ny0 << 4, y1 = (ny1 + 1) << 4;
        int topB = y0 << 10;                       // bytes in top band
        int bandB = topB + ((256 - y1) << 10);     // + bottom band
        int a   = (int)(((long long)bandB * mA / 1000) & ~1023LL);
        int end = (int)(((long long)bandB * mB / 1000) & ~1023LL);
        if (mB == 1000) end = bandB;
        char* rowb = (char*)(out + (size_t)bs * NPIX);
        uint32_t src = smem_u32(zb);
        int off = a;
        while (off < end) {
            int lim = (off < topB) ? topB : bandB;
            int len = min(8192, min(end, lim) - off);
            size_t goff = (off < topB) ? (size_t)off
                                       : ((size_t)(y1 << 10) + (off - topB));
            asm volatile(
                "cp.async.bulk.global.shared::cta.bulk_group [%0], [%1], %2;"
                :: "l"(rowb + goff), "r"(src), "r"(len) : "memory");
            off += len;
        }
        asm volatile("cp.async.bulk.commit_group;" ::: "memory");
        asm volatile("cp.async.bulk.wait_group 0;" ::: "memory");
    }
}

// ---------------------------------------------------------------------------
// A: 288 threads. t<256: centroid means. warp 8: TMA band zero [0,450).
// ---------------------------------------------------------------------------
__global__ void k_cent_init(const float* __restrict__ x, float* __restrict__ out) {
    __shared__ __align__(128) float4 zb[512];     // 8KB zero buffer
    int bs = blockIdx.x;
    int t = threadIdx.x;
    if (t >= 256) {
        tma_zero_bands(out, bs, 0, 450, zb, t & 31);
        return;
    }
    int b = bs >> 8, s = bs & 255;
    int sy = s >> 4, sx = s & 15;
    int warp = t >> 5, lane = t & 31;
    const float* xb = x + (size_t)b * CC * NPIX;
#pragma unroll
    for (int ci = 0; ci < 4; ci++) {
        int c = warp + ci * 8;
        const float* p = xb + (size_t)c * NPIX
                       + (size_t)(sy * SSZ + (lane >> 1)) * WW
                       + sx * SSZ + (lane & 1) * 8;
        float sum = 0.f;
#pragma unroll
        for (int i = 0; i < 8; i++) sum += p[i];
#pragma unroll
        for (int o = 16; o > 0; o >>= 1)
            sum += __shfl_down_sync(0xffffffffu, sum, o);
        if (lane == 0) g_cent[b][s][c] = sum * (1.f / 256.f);
    }
}

// ---------------------------------------------------------------------------
// B: 320 threads. t<288: iter-0 compute (named bar 1). warp 9: TMA [450,850).
// ---------------------------------------------------------------------------
__global__ void k_iter0(const float* __restrict__ x, float* __restrict__ out) {
    __shared__ __align__(16) float px_sh[256][33];
    __shared__ __align__(16) float cent_sh[9][32];
    __shared__ __align__(16) float aff_sh[9][260];
    __shared__ float cnorm_sh[9];
    __shared__ float denp_sh[8][9];
    __shared__ __align__(128) float4 zb[512];

    int b = blockIdx.y, s = blockIdx.x;
    int sy = s >> 4, sx = s & 15;
    int t = threadIdx.x;

    if (t >= 288) {
        tma_zero_bands(out, (b << 8) | s, 450, 850, zb, t & 31);
        return;
    }
    int w = t >> 5, lane = t & 31;

    if (t < 256) {
        const float* xp = x + (size_t)b * CC * NPIX
                        + (size_t)(sy * SSZ + (t >> 4)) * WW
                        + sx * SSZ + (t & 15);
#pragma unroll
        for (int c = 0; c < CC; c++) px_sh[t][c] = xp[(size_t)c * NPIX];
    }
    {
        int ny = sy + w / 3 - 1, nx = sx + w % 3 - 1;
        bool v = ((unsigned)ny < NHH) & ((unsigned)nx < NWW);
        float cv = v ? g_cent[b][ny * NWW + nx][lane] : 0.f;
        cent_sh[w][lane] = cv;
        float cn = cv * cv;
#pragma unroll
        for (int o = 16; o > 0; o >>= 1)
            cn += __shfl_down_sync(0xffffffffu, cn, o);
        if (lane == 0) cnorm_sh[w] = cn;
    }
    BARRIER_COMPUTE();

    if (t < 256) {
        float dot[9];
#pragma unroll
        for (int k = 0; k < 9; k++) dot[k] = 0.f;
        float pnorm = 0.f;
#pragma unroll
        for (int c4 = 0; c4 < 8; c4++) {
            int cb = c4 * 4;
            float p0 = px_sh[t][cb],     p1 = px_sh[t][cb + 1];
            float p2 = px_sh[t][cb + 2], p3 = px_sh[t][cb + 3];
            pnorm = fmaf(p0, p0, fmaf(p1, p1, fmaf(p2, p2, fmaf(p3, p3, pnorm))));
#pragma unroll
            for (int k = 0; k < 9; k++) {
                const float4 cv = *(const float4*)&cent_sh[k][cb];
                dot[k] = fmaf(p0, cv.x, fmaf(p1, cv.y, fmaf(p2, cv.z, fmaf(p3, cv.w, dot[k]))));
            }
        }
        float d[9], dmin = 3.4e38f;
#pragma unroll
        for (int k = 0; k < 9; k++) {
            int ny = sy + k / 3 - 1, nx = sx + k % 3 - 1;
            bool v = ((unsigned)ny < NHH) & ((unsigned)nx < NWW);
            d[k] = fmaf(-2.f, dot[k], pnorm) + cnorm_sh[k];
            if (v && d[k] < dmin) dmin = d[k];
        }
        float e[9], sum = 0.f;
#pragma unroll
        for (int k = 0; k < 9; k++) {
            int ny = sy + k / 3 - 1, nx = sx + k % 3 - 1;
            bool v = ((unsigned)ny < NHH) & ((unsigned)nx < NWW);
            e[k] = v ? expf(dmin - d[k]) : 0.f;
            sum += e[k];
        }
        float inv = 1.f / sum;
#pragma unroll
        for (int k = 0; k < 9; k++) aff_sh[k][t] = e[k] * inv;
    }
    BARRIER_COMPUTE();

    float acc[9];
#pragma unroll
    for (int k = 0; k < 9; k++) acc[k] = 0.f;
    if (t < 256) {
#pragma unroll
        for (int pg = 0; pg < 8; pg++) {
            int p = (w << 5) + (pg << 2);
            float p0 = px_sh[p][lane],     p1 = px_sh[p + 1][lane];
            float p2 = px_sh[p + 2][lane], p3 = px_sh[p + 3][lane];
#pragma unroll
            for (int k = 0; k < 9; k++) {
                const float4 a4 = *(const float4*)&aff_sh[k][p];
                acc[k] = fmaf(a4.x, p0, fmaf(a4.y, p1, fmaf(a4.z, p2, fmaf(a4.w, p3, acc[k]))));
            }
        }
        float dp[9];
#pragma unroll
        for (int k = 0; k < 9; k++) {
            float v = aff_sh[k][(w << 5) + lane];
#pragma unroll
            for (int o = 16; o > 0; o >>= 1)
                v += __shfl_down_sync(0xffffffffu, v, o);
            dp[k] = v;
        }
        if (lane == 0) {
#pragma unroll
            for (int k = 0; k < 9; k++) denp_sh[w][k] = dp[k];
        }
    }
    BARRIER_COMPUTE();
    float* part = &px_sh[0][0];
    if (t < 256) {
#pragma unroll
        for (int k = 0; k < 9; k++) part[(w * 9 + k) * 32 + lane] = acc[k];
    }
    BARRIER_COMPUTE();
    {
        int ny = sy + w / 3 - 1, nx = sx + w % 3 - 1;
        bool v = ((unsigned)ny < NHH) & ((unsigned)nx < NWW);
        if (v) {
            int ns = ny * NWW + nx;
            float num = 0.f;
#pragma unroll
            for (int ww = 0; ww < 8; ww++) num += part[(ww * 9 + w) * 32 + lane];
            g_pnum[b][ns][w][lane] = num;
            if (lane == 0) {
                float den = 0.f;
#pragma unroll
                for (int ww = 0; ww < 8; ww++) den += denp_sh[ww][w];
                g_pden[b][ns][w] = den;
            }
        }
    }
}

// ---------------------------------------------------------------------------
// D: 416 threads. t<288: fused centroid-update + softmax + window scatter.
// warp 9: TMA bands [850,1000). warps 10-12: middle strips + tail (STG).
// ---------------------------------------------------------------------------
__global__ void k_aff_out(const float* __restrict__ x, float* __restrict__ out,
                          float* __restrict__ tailp, int tail_n) {
    __shared__ __align__(16) float px_sh[256][33];
    __shared__ __align__(16) float cent_sh[9][32];
    __shared__ float cnorm_sh[9];
    __shared__ __align__(128) float4 zb[512];

    int b = blockIdx.y, s = blockIdx.x;
    int sy = s >> 4, sx = s & 15;
    int t = threadIdx.x;

    if (t >= 288 && t < 320) {
        tma_zero_bands(out, (b << 8) | s, 850, 1000, zb, t & 31);
        return;
    }
    if (t >= 320) {                         // middle strips + tail
        int tz = t - 320;
        int ny0 = max(sy - 1, 0), ny1 = min(sy + 1, NHH - 1);
        int nx0 = max(sx - 1, 0), nx1 = min(sx + 1, NWW - 1);
        int y0 = ny0 << 4, y1 = (ny1 + 1) << 4;
        int lw = nx0 << 2, xr4 = (nx1 + 1) << 2, rw = 64 - xr4;
        int pr = lw + rw;
        float4* orow = (float4*)(out + ((size_t)((b << 8) | s)) * NPIX);
        const float4 z = make_float4(0.f, 0.f, 0.f, 0.f);
        if (pr > 0) {
            int tot = (y1 - y0) * pr;
            for (int i = tz; i < tot; i += 96) {
                int ry = i / pr, rx = i - ry * pr;
                int col = (rx < lw) ? rx : (xr4 + rx - lw);
                __stcs(orow + ((y0 + ry) << 6) + col, z);
            }
        }
        if (b == 0 && s == 0) {
            for (int i = tz; i < tail_n; i += 96) tailp[i] = 256.0f;
        }
        return;
    }
    int w = t >> 5, lane = t & 31;

    if (t < 256) {
        const float* xp = x + (size_t)b * CC * NPIX
                        + (size_t)(sy * SSZ + (t >> 4)) * WW
                        + sx * SSZ + (t & 15);
#pragma unroll
        for (int c = 0; c < CC; c++) px_sh[t][c] = xp[(size_t)c * NPIX];
    }
    {
        int ny = sy + w / 3 - 1, nx = sx + w % 3 - 1;
        bool v = ((unsigned)ny < NHH) & ((unsigned)nx < NWW);
        float cv = 0.f;
        if (v) {
            int ns = ny * NWW + nx;
            float num = 0.f;
#pragma unroll
            for (int k = 0; k < 9; k++) {
                int ty = ny - (k / 3 - 1), tx = nx - (k % 3 - 1);
                if (((unsigned)ty < NHH) & ((unsigned)tx < NWW))
                    num += g_pnum[b][ns][k][lane];
            }
            float dl = 0.f;
            if (lane < 9) {
                int ty = ny - (lane / 3 - 1), tx = nx - (lane % 3 - 1);
                if (((unsigned)ty < NHH) & ((unsigned)tx < NWW))
                    dl = g_pden[b][ns][lane];
            }
#pragma unroll
            for (int o = 16; o > 0; o >>= 1)
                dl += __shfl_down_sync(0xffffffffu, dl, o);
            float den = __shfl_sync(0xffffffffu, dl, 0);
            cv = num / (den + 1e-16f);
        }
        cent_sh[w][lane] = cv;
        float cn = cv * cv;
#pragma unroll
        for (int o = 16; o > 0; o >>= 1)
            cn += __shfl_down_sync(0xffffffffu, cn, o);
        if (lane == 0) cnorm_sh[w] = cn;
    }
    BARRIER_COMPUTE();

    if (t < 256) {
        float dot[9];
#pragma unroll
        for (int k = 0; k < 9; k++) dot[k] = 0.f;
        float pnorm = 0.f;
#pragma unroll
        for (int c4 = 0; c4 < 8; c4++) {
            int cb = c4 * 4;
            float p0 = px_sh[t][cb],     p1 = px_sh[t][cb + 1];
            float p2 = px_sh[t][cb + 2], p3 = px_sh[t][cb + 3];
            pnorm = fmaf(p0, p0, fmaf(p1, p1, fmaf(p2, p2, fmaf(p3, p3, pnorm))));
#pragma unroll
            for (int k = 0; k < 9; k++) {
                const float4 cv = *(const float4*)&cent_sh[k][cb];
                dot[k] = fmaf(p0, cv.x, fmaf(p1, cv.y, fmaf(p2, cv.z, fmaf(p3, cv.w, dot[k]))));
            }
        }
        float d[9], dmin = 3.4e38f;
#pragma unroll
        for (int k = 0; k < 9; k++) {
            int ny = sy + k / 3 - 1, nx = sx + k % 3 - 1;
            bool v = ((unsigned)ny < NHH) & ((unsigned)nx < NWW);
            d[k] = fmaf(-2.f, dot[k], pnorm) + cnorm_sh[k];
            if (v && d[k] < dmin) dmin = d[k];
        }
        float e[9], sum = 0.f;
#pragma unroll
        for (int k = 0; k < 9; k++) {
            int ny = sy + k / 3 - 1, nx = sx + k % 3 - 1;
            bool v = ((unsigned)ny < NHH) & ((unsigned)nx < NWW);
            e[k] = v ? expf(dmin - d[k]) : 0.f;
            sum += e[k];
        }
        float inv = 1.f / sum;

        int n = (sy * SSZ + (t >> 4)) * WW + sx * SSZ + (t & 15);
        size_t obase = (size_t)b * SP * NPIX + (size_t)n;
#pragma unroll
        for (int k = 0; k < 9; k++) {
            int ny = sy + k / 3 - 1, nx = sx + k % 3 - 1;
            bool v = ((unsigned)ny < NHH) & ((unsigned)nx < NWW);
            if (v) out[obase + (size_t)(ny * NWW + nx) * NPIX] = e[k] * inv;
        }
    }
}

extern "C" void kernel_launch(void* const* d_in, const int* in_sizes, int n_in,
                              void* d_out, int out_size) {
    const float* x = (const float*)d_in[0];
    float* out = (float*)d_out;
    dim3 grid(SP, BB);

    long long total = (long long)BB * SP * NPIX;
    int tail_n = (int)(((long long)out_size > total) ? ((long long)out_size - total) : 0);

    k_cent_init<<<BB * SP, 288>>>(x, out);
    k_iter0<<<grid, 320>>>(x, out);
    k_aff_out<<<grid, 416>>>(x, out, out + total, tail_n);
}

// round 14
// speedup vs baseline: 1.4924x; 1.4924x over previous
#include <cuda_runtime.h>

#define BB   4
#define CC   32
#define HH   256
#define WW   256
#define SSZ  16
#define NHH  16
#define NWW  16
#define SP   256
#define NPIX 65536

__device__ float g_cent[BB][SP][CC];
__device__ float g_pnum[BB][SP][9][CC];
__device__ float g_pden[BB][SP][9];

#define BARRIER_COMPUTE() asm volatile("bar.sync 1, 288;" ::: "memory")

// ---------------------------------------------------------------------------
// Band zeroing: top+bottom full-width bands of row (b,s), linearized float4
// range [mA,mB) per-mille. Contiguous, predicate-free, __stcs.
// ---------------------------------------------------------------------------
__device__ __forceinline__ void zero_bands(float* __restrict__ out, int bs,
                                           int mA, int mB, int t, int nthr) {
    int s = bs & 255;
    int sy = s >> 4;
    int ny0 = max(sy - 1, 0), ny1 = min(sy + 1, NHH - 1);
    int y0 = ny0 << 4, y1 = (ny1 + 1) << 4;
    int topN = y0 << 6;
    int bandN = topN + (16384 - (y1 << 6));
    int a   = (int)((long long)bandN * mA / 1000);
    int end = (mB == 1000) ? bandN : (int)((long long)bandN * mB / 1000);
    float4* orow = (float4*)(out + (size_t)bs * NPIX);
    const float4 z = make_float4(0.f, 0.f, 0.f, 0.f);
    for (int i = a + t; i < end; i += nthr) {
        int idx = (i < topN) ? i : ((y1 << 6) + (i - topN));
        __stcs(orow + idx, z);
    }
}

// Middle strips (rows [y0,y1), cols outside window), half = 0 or 1.
__device__ __forceinline__ void zero_strips(float* __restrict__ out, int bs,
                                            int half, int t, int nthr) {
    int s = bs & 255;
    int sy = s >> 4, sx = s & 15;
    int ny0 = max(sy - 1, 0), ny1 = min(sy + 1, NHH - 1);
    int nx0 = max(sx - 1, 0), nx1 = min(sx + 1, NWW - 1);
    int y0 = ny0 << 4, y1 = (ny1 + 1) << 4;
    int lw = nx0 << 2, xr4 = (nx1 + 1) << 2, rw = 64 - xr4;
    int pr = lw + rw;
    if (pr <= 0) return;
    int tot = (y1 - y0) * pr;
    int a = half ? tot / 2 : 0;
    int end = half ? tot : tot / 2;
    float4* orow = (float4*)(out + (size_t)bs * NPIX);
    const float4 z = make_float4(0.f, 0.f, 0.f, 0.f);
    for (int i = a + t; i < end; i += nthr) {
        int ry = i / pr, rx = i - ry * pr;
        int col = (rx < lw) ? rx : (xr4 + rx - lw);
        __stcs(orow + ((y0 + ry) << 6) + col, z);
    }
}

// ---------------------------------------------------------------------------
// A: 512 threads. t<256: centroid means. t>=256: zero bands [0,500).
// ---------------------------------------------------------------------------
__global__ void k_cent_init(const float* __restrict__ x, float* __restrict__ out) {
    int bs = blockIdx.x;
    int t = threadIdx.x;
    if (t >= 256) {
        zero_bands(out, bs, 0, 500, t - 256, 256);
        return;
    }
    int b = bs >> 8, s = bs & 255;
    int sy = s >> 4, sx = s & 15;
    int warp = t >> 5, lane = t & 31;
    const float* xb = x + (size_t)b * CC * NPIX;
#pragma unroll
    for (int ci = 0; ci < 4; ci++) {
        int c = warp + ci * 8;
        const float* p = xb + (size_t)c * NPIX
                       + (size_t)(sy * SSZ + (lane >> 1)) * WW
                       + sx * SSZ + (lane & 1) * 8;
        float sum = 0.f;
#pragma unroll
        for (int i = 0; i < 8; i++) sum += p[i];
#pragma unroll
        for (int o = 16; o > 0; o >>= 1)
            sum += __shfl_down_sync(0xffffffffu, sum, o);
        if (lane == 0) g_cent[b][s][c] = sum * (1.f / 256.f);
    }
}

// ---------------------------------------------------------------------------
// B: 544 threads. t<288: iter-0 compute (named bar 1, 288). t>=288: 8 zero
// warps: bands [500,750) + strips half 0.
// ---------------------------------------------------------------------------
__global__ void k_iter0(const float* __restrict__ x, float* __restrict__ out) {
    __shared__ __align__(16) float px_sh[256][33];
    __shared__ __align__(16) float cent_sh[9][32];
    __shared__ __align__(16) float aff_sh[9][260];
    __shared__ float cnorm_sh[9];
    __shared__ float denp_sh[8][9];

    int b = blockIdx.y, s = blockIdx.x;
    int sy = s >> 4, sx = s & 15;
    int t = threadIdx.x;

    if (t >= 288) {
        int tz = t - 288, bsi = (b << 8) | s;
        zero_bands(out, bsi, 500, 750, tz, 256);
        zero_strips(out, bsi, 0, tz, 256);
        return;
    }
    int w = t >> 5, lane = t & 31;

    if (t < 256) {
        const float* xp = x + (size_t)b * CC * NPIX
                        + (size_t)(sy * SSZ + (t >> 4)) * WW
                        + sx * SSZ + (t & 15);
#pragma unroll
        for (int c = 0; c < CC; c++) px_sh[t][c] = xp[(size_t)c * NPIX];
    }
    {
        int ny = sy + w / 3 - 1, nx = sx + w % 3 - 1;
        bool v = ((unsigned)ny < NHH) & ((unsigned)nx < NWW);
        float cv = v ? g_cent[b][ny * NWW + nx][lane] : 0.f;
        cent_sh[w][lane] = cv;
        float cn = cv * cv;
#pragma unroll
        for (int o = 16; o > 0; o >>= 1)
            cn += __shfl_down_sync(0xffffffffu, cn, o);
        if (lane == 0) cnorm_sh[w] = cn;
    }
    BARRIER_COMPUTE();

    if (t < 256) {
        float dot[9];
#pragma unroll
        for (int k = 0; k < 9; k++) dot[k] = 0.f;
        float pnorm = 0.f;
#pragma unroll
        for (int c4 = 0; c4 < 8; c4++) {
            int cb = c4 * 4;
            float p0 = px_sh[t][cb],     p1 = px_sh[t][cb + 1];
            float p2 = px_sh[t][cb + 2], p3 = px_sh[t][cb + 3];
            pnorm = fmaf(p0, p0, fmaf(p1, p1, fmaf(p2, p2, fmaf(p3, p3, pnorm))));
#pragma unroll
            for (int k = 0; k < 9; k++) {
                const float4 cv = *(const float4*)&cent_sh[k][cb];
                dot[k] = fmaf(p0, cv.x, fmaf(p1, cv.y, fmaf(p2, cv.z, fmaf(p3, cv.w, dot[k]))));
            }
        }
        float d[9], dmin = 3.4e38f;
#pragma unroll
        for (int k = 0; k < 9; k++) {
            int ny = sy + k / 3 - 1, nx = sx + k % 3 - 1;
            bool v = ((unsigned)ny < NHH) & ((unsigned)nx < NWW);
            d[k] = fmaf(-2.f, dot[k], pnorm) + cnorm_sh[k];
            if (v && d[k] < dmin) dmin = d[k];
        }
        float e[9], sum = 0.f;
#pragma unroll
        for (int k = 0; k < 9; k++) {
            int ny = sy + k / 3 - 1, nx = sx + k % 3 - 1;
            bool v = ((unsigned)ny < NHH) & ((unsigned)nx < NWW);
            e[k] = v ? expf(dmin - d[k]) : 0.f;
            sum += e[k];
        }
        float inv = 1.f / sum;
#pragma unroll
        for (int k = 0; k < 9; k++) aff_sh[k][t] = e[k] * inv;
    }
    BARRIER_COMPUTE();

    float acc[9];
#pragma unroll
    for (int k = 0; k < 9; k++) acc[k] = 0.f;
    if (t < 256) {
#pragma unroll
        for (int pg = 0; pg < 8; pg++) {
            int p = (w << 5) + (pg << 2);
            float p0 = px_sh[p][lane],     p1 = px_sh[p + 1][lane];
            float p2 = px_sh[p + 2][lane], p3 = px_sh[p + 3][lane];
#pragma unroll
            for (int k = 0; k < 9; k++) {
                const float4 a4 = *(const float4*)&aff_sh[k][p];
                acc[k] = fmaf(a4.x, p0, fmaf(a4.y, p1, fmaf(a4.z, p2, fmaf(a4.w, p3, acc[k]))));
            }
        }
        float dp[9];
#pragma unroll
        for (int k = 0; k < 9; k++) {
            float v = aff_sh[k][(w << 5) + lane];
#pragma unroll
            for (int o = 16; o > 0; o >>= 1)
                v += __shfl_down_sync(0xffffffffu, v, o);
            dp[k] = v;
        }
        if (lane == 0) {
#pragma unroll
            for (int k = 0; k < 9; k++) denp_sh[w][k] = dp[k];
        }
    }
    BARRIER_COMPUTE();
    float* part = &px_sh[0][0];
    if (t < 256) {
#pragma unroll
        for (int k = 0; k < 9; k++) part[(w * 9 + k) * 32 + lane] = acc[k];
    }
    BARRIER_COMPUTE();
    {
        int ny = sy + w / 3 - 1, nx = sx + w % 3 - 1;
        bool v = ((unsigned)ny < NHH) & ((unsigned)nx < NWW);
        if (v) {
            int ns = ny * NWW + nx;
            float num = 0.f;
#pragma unroll
            for (int ww = 0; ww < 8; ww++) num += part[(ww * 9 + w) * 32 + lane];
            g_pnum[b][ns][w][lane] = num;
            if (lane == 0) {
                float den = 0.f;
#pragma unroll
                for (int ww = 0; ww < 8; ww++) den += denp_sh[ww][w];
                g_pden[b][ns][w] = den;
            }
        }
    }
}

// ---------------------------------------------------------------------------
// D: 544 threads. t<288: fused centroid-update + softmax + window scatter.
// t>=288: 8 zero warps: bands [750,1000) + strips half 1 + tail.
// ---------------------------------------------------------------------------
__global__ void k_aff_out(const float* __restrict__ x, float* __restrict__ out,
                          float* __restrict__ tailp, int tail_n) {
    __shared__ __align__(16) float px_sh[256][33];
    __shared__ __align__(16) float cent_sh[9][32];
    __shared__ float cnorm_sh[9];

    int b = blockIdx.y, s = blockIdx.x;
    int sy = s >> 4, sx = s & 15;
    int t = threadIdx.x;

    if (t >= 288) {
        int tz = t - 288, bsi = (b << 8) | s;
        zero_bands(out, bsi, 750, 1000, tz, 256);
        zero_strips(out, bsi, 1, tz, 256);
        if (bsi == 0) {
            for (int i = tz; i < tail_n; i += 256) tailp[i] = 256.0f;
        }
        return;
    }
    int w = t >> 5, lane = t & 31;

    if (t < 256) {
        const float* xp = x + (size_t)b * CC * NPIX
                        + (size_t)(sy * SSZ + (t >> 4)) * WW
                        + sx * SSZ + (t & 15);
#pragma unroll
        for (int c = 0; c < CC; c++) px_sh[t][c] = xp[(size_t)c * NPIX];
    }
    {
        int ny = sy + w / 3 - 1, nx = sx + w % 3 - 1;
        bool v = ((unsigned)ny < NHH) & ((unsigned)nx < NWW);
        float cv = 0.f;
        if (v) {
            int ns = ny * NWW + nx;
            float num = 0.f;
#pragma unroll
            for (int k = 0; k < 9; k++) {
                int ty = ny - (k / 3 - 1), tx = nx - (k % 3 - 1);
                if (((unsigned)ty < NHH) & ((unsigned)tx < NWW))
                    num += g_pnum[b][ns][k][lane];
            }
            float dl = 0.f;
            if (lane < 9) {
                int ty = ny - (lane / 3 - 1), tx = nx - (lane % 3 - 1);
                if (((unsigned)ty < NHH) & ((unsigned)tx < NWW))
                    dl = g_pden[b][ns][lane];
            }
#pragma unroll
            for (int o = 16; o > 0; o >>= 1)
                dl += __shfl_down_sync(0xffffffffu, dl, o);
            float den = __shfl_sync(0xffffffffu, dl, 0);
            cv = num / (den + 1e-16f);
        }
        cent_sh[w][lane] = cv;
        float cn = cv * cv;
#pragma unroll
        for (int o = 16; o > 0; o >>= 1)
            cn += __shfl_down_sync(0xffffffffu, cn, o);
        if (lane == 0) cnorm_sh[w] = cn;
    }
    BARRIER_COMPUTE();

    if (t < 256) {
        float dot[9];
#pragma unroll
        for (int k = 0; k < 9; k++) dot[k] = 0.f;
        float pnorm = 0.f;
#pragma unroll
        for (int c4 = 0; c4 < 8; c4++) {
            int cb = c4 * 4;
            float p0 = px_sh[t][cb],     p1 = px_sh[t][cb + 1];
            float p2 = px_sh[t][cb + 2], p3 = px_sh[t][cb + 3];
            pnorm = fmaf(p0, p0, fmaf(p1, p1, fmaf(p2, p2, fmaf(p3, p3, pnorm))));
#pragma unroll
            for (int k = 0; k < 9; k++) {
                const float4 cv = *(const float4*)&cent_sh[k][cb];
                dot[k] = fmaf(p0, cv.x, fmaf(p1, cv.y, fmaf(p2, cv.z, fmaf(p3, cv.w, dot[k]))));
            }
        }
        float d[9], dmin = 3.4e38f;
#pragma unroll
        for (int k = 0; k < 9; k++) {
            int ny = sy + k / 3 - 1, nx = sx + k % 3 - 1;
            bool v = ((unsigned)ny < NHH) & ((unsigned)nx < NWW);
            d[k] = fmaf(-2.f, dot[k], pnorm) + cnorm_sh[k];
            if (v && d[k] < dmin) dmin = d[k];
        }
        float e[9], sum = 0.f;
#pragma unroll
        for (int k = 0; k < 9; k++) {
            int ny = sy + k / 3 - 1, nx = sx + k % 3 - 1;
            bool v = ((unsigned)ny < NHH) & ((unsigned)nx < NWW);
            e[k] = v ? expf(dmin - d[k]) : 0.f;
            sum += e[k];
        }
        float inv = 1.f / sum;

        int n = (sy * SSZ + (t >> 4)) * WW + sx * SSZ + (t & 15);
        size_t obase = (size_t)b * SP * NPIX + (size_t)n;
#pragma unroll
        for (int k = 0; k < 9; k++) {
            int ny = sy + k / 3 - 1, nx = sx + k % 3 - 1;
            bool v = ((unsigned)ny < NHH) & ((unsigned)nx < NWW);
            if (v) out[obase + (size_t)(ny * NWW + nx) * NPIX] = e[k] * inv;
        }
    }
}

extern "C" void kernel_launch(void* const* d_in, const int* in_sizes, int n_in,
                              void* d_out, int out_size) {
    const float* x = (const float*)d_in[0];
    float* out = (float*)d_out;
    dim3 grid(SP, BB);

    long long total = (long long)BB * SP * NPIX;
    int tail_n = (int)(((long long)out_size > total) ? ((long long)out_size - total) : 0);

    k_cent_init<<<BB * SP, 512>>>(x, out);
    k_iter0<<<grid, 544>>>(x, out);
    k_aff_out<<<grid, 544>>>(x, out, out + total, tail_n);
}